// round 7
// baseline (speedup 1.0000x reference)
#include <cuda_runtime.h>
#include <cuda_bf16.h>
#include <cstdint>

// ---------------------------------------------------------------------------
// SharedGroupGRU: B=16384 rows, IN=HID=128, KEY=64, RULES=16.
//   att == y_hard (argmax of logits+gumbel); logits[b,r] = q[b].hnext[b,r],
//   q = H @ (w_read @ W_write).
// Round 7: bf16-split HMMA (hh+hl+lh, fp32 accum) — back to 512 threads /
// 128 regs (known-good ILP), warp tile widened to 32 rows x 32 cols so B
// fragments are reused across 2x rows: LDSM bytes 2.0MB -> 1.31MB per CTA.
// Logits in kGRU epilogue; gather-only select.
// ---------------------------------------------------------------------------

#define BTOT   16384
#define KDIM   128
#define RULES  16
#define TM     64
#define NA     (BTOT * KDIM)          // 2,097,152
#define NW     (RULES * 384 * KDIM)   // 786,432

typedef unsigned long long u64;

// -------------------- device scratch (static; no runtime alloc) ------------
__device__ float g_M[KDIM * KDIM];
__device__ float g_q[BTOT * KDIM];
__device__ float g_logits[BTOT * RULES];
__device__ float g_hnext[(size_t)BTOT * RULES * KDIM];

// A slabs: arr 0=Xh 1=Xl 2=Hh 3=Hl, each [BTOT][128]
__device__ __nv_bfloat16 g_Asp[4 * NA];
// W slabs: arr = (s*3+g)*2 + lvl, each [RULES][128][128]
__device__ __nv_bfloat16 g_Wsp[12 * RULES * 128 * KDIM];

// -------------------- helpers ----------------------------------------------
__device__ __forceinline__ uint32_t smem_u32(const void* p) {
    uint32_t a;
    asm("{ .reg .u64 t; cvta.to.shared.u64 t, %1; cvt.u32.u64 %0, t; }" : "=r"(a) : "l"(p));
    return a;
}
__device__ __forceinline__ void cpasync16(uint32_t dst, const void* src) {
    asm volatile("cp.async.cg.shared.global [%0], [%1], 16;" :: "r"(dst), "l"(src));
}
__device__ __forceinline__ void ldsm4(uint32_t* r, uint32_t a) {
    asm volatile("ldmatrix.sync.aligned.m8n8.x4.shared.b16 {%0,%1,%2,%3}, [%4];"
                 : "=r"(r[0]), "=r"(r[1]), "=r"(r[2]), "=r"(r[3]) : "r"(a));
}
__device__ __forceinline__ void mma16816(float* d, const uint32_t* a, const uint32_t* b) {
    asm volatile("mma.sync.aligned.m16n8k16.row.col.f32.bf16.bf16.f32 "
                 "{%0,%1,%2,%3}, {%4,%5,%6,%7}, {%8,%9}, {%0,%1,%2,%3};"
                 : "+f"(d[0]), "+f"(d[1]), "+f"(d[2]), "+f"(d[3])
                 : "r"(a[0]), "r"(a[1]), "r"(a[2]), "r"(a[3]), "r"(b[0]), "r"(b[1]));
}
__device__ __forceinline__ float sigf(float x) {
    return __fdividef(1.0f, 1.0f + __expf(-x));
}
__device__ __forceinline__ float tanhf_fast(float x) {
    float e = __expf(2.0f * x);
    return 1.0f - __fdividef(2.0f, e + 1.0f);
}

// -------------------- smem geometry ----------------------------------------
#define A_SZ        4096               // 64 rows x 32 k bf16 (64B rows)
#define B_SZ        8192               // 128 rows x 32 k bf16
#define B_OFF       16384              // after 4 A tiles
#define STAGE_BYTES 114688             // 112KB
#define SMEM_TOTAL  (2 * STAGE_BYTES)  // 224KB
// epilogue staging: 4 planes x 64 x 132 fp32 (reuses stage smem)
#define STG_PITCH   132
#define STG_PLANE   (64 * STG_PITCH)

// ---------------------------------------------------------------------------
// kPre: conversions + M (last block).
// ---------------------------------------------------------------------------
__global__ void kPre(const float* __restrict__ X, const float* __restrict__ H,
                     const float* __restrict__ Wih, const float* __restrict__ Whh,
                     const float* __restrict__ wread, const float* __restrict__ wwrite) {
    if (blockIdx.x == gridDim.x - 1) {
        for (int o = threadIdx.x; o < KDIM * KDIM; o += blockDim.x) {
            int hp = o >> 7, h = o & 127;
            float s = 0.0f;
            #pragma unroll 8
            for (int k = 0; k < 64; ++k)
                s = fmaf(wread[hp * 64 + k], wwrite[k * 128 + h], s);
            g_M[o] = s;
        }
        return;
    }
    int i = blockIdx.x * blockDim.x + threadIdx.x;
    if (i < NA) {
        float v = X[i];
        __nv_bfloat16 h = __float2bfloat16(v);
        g_Asp[i] = h;
        g_Asp[NA + i] = __float2bfloat16(v - __bfloat162float(h));
        v = H[i];
        h = __float2bfloat16(v);
        g_Asp[2 * NA + i] = h;
        g_Asp[3 * NA + i] = __float2bfloat16(v - __bfloat162float(h));
    }
    if (i < NW) {
        int rule = i / 49152;
        int rem  = i - rule * 49152;
        int row384 = rem >> 7, k = rem & 127;
        int g = row384 >> 7, rowg = row384 & 127;
        size_t dst = ((size_t)rule * 128 + rowg) * 128 + k;
        const size_t AS = (size_t)RULES * 128 * 128;
        float v = Wih[i];
        __nv_bfloat16 h = __float2bfloat16(v);
        g_Wsp[(size_t)(g * 2) * AS + dst] = h;
        g_Wsp[(size_t)(g * 2 + 1) * AS + dst] = __float2bfloat16(v - __bfloat162float(h));
        v = Whh[i];
        h = __float2bfloat16(v);
        g_Wsp[(size_t)((3 + g) * 2) * AS + dst] = h;
        g_Wsp[(size_t)((3 + g) * 2 + 1) * AS + dst] = __float2bfloat16(v - __bfloat162float(h));
    }
}

// ---------------------------------------------------------------------------
// kQ: g_q = H @ g_M (fp32; feeds argmax path)
// ---------------------------------------------------------------------------
__global__ void kQ(const float* __restrict__ Hin) {
    __shared__ float Hs[16][KDIM];
    int b0 = blockIdx.x * 16;
    for (int i = threadIdx.x; i < 16 * KDIM; i += blockDim.x)
        Hs[i >> 7][i & 127] = Hin[b0 * KDIM + i];
    __syncthreads();

    int h  = threadIdx.x & 127;
    int rr = threadIdx.x >> 7;
    float acc[8];
    #pragma unroll
    for (int j = 0; j < 8; ++j) acc[j] = 0.0f;
    for (int k = 0; k < KDIM; ++k) {
        float m = g_M[k * KDIM + h];
        #pragma unroll
        for (int j = 0; j < 8; ++j)
            acc[j] = fmaf(Hs[rr + 2 * j][k], m, acc[j]);
    }
    #pragma unroll
    for (int j = 0; j < 8; ++j)
        g_q[(size_t)(b0 + rr + 2 * j) * KDIM + h] = acc[j];
}

// ---------------------------------------------------------------------------
// kGRU stage loader: 512 threads, 14 x cp.async(16B) each.
// ---------------------------------------------------------------------------
__device__ __forceinline__ void load_stage(uint32_t stb, int b0, int rule,
                                           int tid, int k0) {
    // A: 4 tiles x 64 rows x 4 chunks = 1024 ops (2/thread)
    #pragma unroll
    for (int it = 0; it < 2; ++it) {
        int idx = it * 512 + tid;
        int tile = idx >> 8;
        int row  = (idx >> 2) & 63;
        int cc   = idx & 3;
        uint32_t sw = (uint32_t)((cc ^ ((row >> 1) & 3)) << 4);
        const __nv_bfloat16* src =
            g_Asp + (size_t)tile * NA + (size_t)(b0 + row) * KDIM + k0 + cc * 8;
        cpasync16(stb + tile * A_SZ + row * 64 + sw, src);
    }
    // B: 12 arrs x 128 rows x 4 chunks = 6144 ops (12/thread)
    #pragma unroll
    for (int a = 0; a < 12; ++a) {
        int idx = a * 512 + tid;
        int arr = idx >> 9;
        int row = (idx >> 2) & 127;
        int cc  = idx & 3;
        uint32_t sw = (uint32_t)((cc ^ ((row >> 1) & 3)) << 4);
        const __nv_bfloat16* src =
            g_Wsp + ((size_t)arr * RULES + rule) * (128 * KDIM) + (size_t)row * KDIM + k0 + cc * 8;
        cpasync16(stb + B_OFF + arr * B_SZ + row * 64 + sw, src);
    }
    asm volatile("cp.async.commit_group;" ::: "memory");
}

// ---------------------------------------------------------------------------
// kGRU: grid (256, 16), block 512 = 16 warps.
// Warp w: rg = w&1 (32-row half, 2 mtiles), u = w>>1: gh = u>>2 (0=r,1=z),
// n-quarter = (u&3)*32 (4 ntiles as 2 ldsm4 pairs).
// accH[2 mt][4 nt][4], accL[2][4][4] = 64 fp32/thread. Light plane on s==gh.
// ---------------------------------------------------------------------------
__global__ void __launch_bounds__(512, 1)
kGRU(const float* __restrict__ Hin,
     const float* __restrict__ bih, const float* __restrict__ bhh) {
    extern __shared__ char smem[];
    const uint32_t sb = smem_u32(smem);
    const int tid = threadIdx.x;
    const int w = tid >> 5, lane = tid & 31;
    const int b0 = blockIdx.x * TM;
    const int rule = blockIdx.y;

    const int rg = w & 1;
    const int u  = w >> 1;
    const int gh = u >> 2;
    const int n0 = (u & 3) * 32;

    // A ldsm4 addressing (mt adds 16 rows = +1024B; swizzle class unchanged)
    const int rowa0 = rg * 32 + ((lane >> 3) & 1) * 8 + (lane & 7);
    const uint32_t aoff0 = (uint32_t)rowa0 * 64;
    const int swa = (rowa0 >> 1) & 3;
    const int hiA = lane >> 4;
    // B ldsm4 addressing: pair p covers n-tiles 2p, 2p+1 (16 rows)
    const int nbase = n0 + ((lane >> 4) & 1) * 8 + (lane & 7);
    const uint32_t boff0 = (uint32_t)nbase * 64;
    const uint32_t boff1 = (uint32_t)(nbase + 16) * 64;
    const int swb = (nbase >> 1) & 3;   // (nbase+16): same class mod 4
    const int hiB = (lane >> 3) & 1;

    float accH[2][4][4], accL[2][4][4];
    #pragma unroll
    for (int mt = 0; mt < 2; ++mt)
        #pragma unroll
        for (int nt = 0; nt < 4; ++nt)
            #pragma unroll
            for (int j = 0; j < 4; ++j) { accH[mt][nt][j] = 0.0f; accL[mt][nt][j] = 0.0f; }

    load_stage(sb, b0, rule, tid, 0);
    load_stage(sb + STAGE_BYTES, b0, rule, tid, 32);

    for (int c = 0; c < 4; ++c) {
        if (c < 3) asm volatile("cp.async.wait_group 1;" ::: "memory");
        else       asm volatile("cp.async.wait_group 0;" ::: "memory");
        __syncthreads();

        const uint32_t stb = sb + (c & 1) * STAGE_BYTES;
        #pragma unroll
        for (int ks = 0; ks < 2; ++ks) {
            const uint32_t kxa = (uint32_t)(((ks * 2 + hiA) ^ swa) << 4);
            const uint32_t kxb = (uint32_t)(((ks * 2 + hiB) ^ swb) << 4);
            #pragma unroll
            for (int s = 0; s < 2; ++s) {
                uint32_t ah[2][4], al[2][4];
                const uint32_t abase = stb + (uint32_t)(s * 2) * A_SZ;
                ldsm4(ah[0], abase + aoff0 + kxa);
                ldsm4(ah[1], abase + aoff0 + 1024 + kxa);
                ldsm4(al[0], abase + A_SZ + aoff0 + kxa);
                ldsm4(al[1], abase + A_SZ + aoff0 + 1024 + kxa);

                const uint32_t hb = stb + B_OFF + (uint32_t)((s * 3 + gh) * 2) * B_SZ;
                #pragma unroll
                for (int p = 0; p < 2; ++p) {
                    uint32_t bh[4], bl[4];
                    const uint32_t bo = (p ? boff1 : boff0) + kxb;
                    ldsm4(bh, hb + bo);
                    ldsm4(bl, hb + B_SZ + bo);
                    #pragma unroll
                    for (int mt = 0; mt < 2; ++mt) {
                        mma16816(accH[mt][2*p+0], ah[mt], bh + 0);
                        mma16816(accH[mt][2*p+0], ah[mt], bl + 0);
                        mma16816(accH[mt][2*p+0], al[mt], bh + 0);
                        mma16816(accH[mt][2*p+1], ah[mt], bh + 2);
                        mma16816(accH[mt][2*p+1], ah[mt], bl + 2);
                        mma16816(accH[mt][2*p+1], al[mt], bh + 2);
                    }
                }
                if (s == gh) {   // light plane: i_n (s=0) / h_n (s=1)
                    const uint32_t lb = stb + B_OFF + (uint32_t)((s * 3 + 2) * 2) * B_SZ;
                    #pragma unroll
                    for (int p = 0; p < 2; ++p) {
                        uint32_t bh[4], bl[4];
                        const uint32_t bo = (p ? boff1 : boff0) + kxb;
                        ldsm4(bh, lb + bo);
                        ldsm4(bl, lb + B_SZ + bo);
                        #pragma unroll
                        for (int mt = 0; mt < 2; ++mt) {
                            mma16816(accL[mt][2*p+0], ah[mt], bh + 0);
                            mma16816(accL[mt][2*p+0], ah[mt], bl + 0);
                            mma16816(accL[mt][2*p+0], al[mt], bh + 0);
                            mma16816(accL[mt][2*p+1], ah[mt], bh + 2);
                            mma16816(accL[mt][2*p+1], ah[mt], bl + 2);
                            mma16816(accL[mt][2*p+1], al[mt], bh + 2);
                        }
                    }
                }
            }
        }
        if (c < 2) {
            __syncthreads();
            load_stage(sb + (c & 1) * STAGE_BYTES, b0, rule, tid, (c + 2) * 32);
        }
    }
    __syncthreads();

    // ---- stage accums: planes r,z,i_n,h_n at pitch 132
    float* stg = (float*)smem;
    {
        const int pcolb = n0 + (lane & 3) * 2;
        #pragma unroll
        for (int mt = 0; mt < 2; ++mt) {
            const int prow = rg * 32 + mt * 16 + (lane >> 2);
            #pragma unroll
            for (int nt = 0; nt < 4; ++nt) {
                float* pH = stg + gh * STG_PLANE + prow * STG_PITCH + pcolb + nt * 8;
                pH[0] = accH[mt][nt][0]; pH[1] = accH[mt][nt][1];
                pH[8 * STG_PITCH] = accH[mt][nt][2]; pH[8 * STG_PITCH + 1] = accH[mt][nt][3];
                float* pL = stg + (2 + gh) * STG_PLANE + prow * STG_PITCH + pcolb + nt * 8;
                pL[0] = accL[mt][nt][0]; pL[1] = accL[mt][nt][1];
                pL[8 * STG_PITCH] = accL[mt][nt][2]; pL[8 * STG_PITCH + 1] = accL[mt][nt][3];
            }
        }
    }
    __syncthreads();

    // ---- gates + logits + store: thread -> (row, 16 cols)
    {
        const int row = tid >> 3;
        const int c0  = (tid & 7) * 16;
        const size_t bg = (size_t)(b0 + row);
        const float* bi = bih + rule * 384;
        const float* bh = bhh + rule * 384;
        const float* hprow = Hin + bg * KDIM;
        const float* qrow  = g_q + bg * KDIM;
        float out[16];
        float dot = 0.0f;
        #pragma unroll
        for (int q = 0; q < 16; ++q) {
            int cc = c0 + q;
            float ar  = stg[                row * STG_PITCH + cc] + bi[cc] + bh[cc];
            float az  = stg[STG_PLANE +     row * STG_PITCH + cc] + bi[128 + cc] + bh[128 + cc];
            float xin = stg[2 * STG_PLANE + row * STG_PITCH + cc] + bi[256 + cc];
            float xhn = stg[3 * STG_PLANE + row * STG_PITCH + cc] + bh[256 + cc];
            float rgate = sigf(ar);
            float zgate = sigf(az);
            float nn = tanhf_fast(fmaf(rgate, xhn, xin));
            out[q] = fmaf(zgate, hprow[cc] - nn, nn);
            dot = fmaf(qrow[cc], out[q], dot);
        }
        dot += __shfl_xor_sync(0xffffffffu, dot, 4);
        dot += __shfl_xor_sync(0xffffffffu, dot, 2);
        dot += __shfl_xor_sync(0xffffffffu, dot, 1);
        if ((tid & 7) == 0)
            g_logits[bg * RULES + rule] = dot;

        float* dst = g_hnext + (bg * RULES + rule) * KDIM + c0;
        #pragma unroll
        for (int q4 = 0; q4 < 4; ++q4)
            *reinterpret_cast<float4*>(dst + q4 * 4) =
                *reinterpret_cast<const float4*>(&out[q4 * 4]);
    }
}

// ---------------------------------------------------------------------------
// kSelect: gather-only. One warp per b.
// ---------------------------------------------------------------------------
__global__ void kSelect(const float* __restrict__ gumbel,
                        float* __restrict__ out_h, float* __restrict__ out_attn) {
    int gwarp = (blockIdx.x * blockDim.x + threadIdx.x) >> 5;
    int lane = threadIdx.x & 31;
    if (gwarp >= BTOT) return;
    const int b = gwarp;

    float bv = -__int_as_float(0x7f800000);
    if (lane < RULES)
        bv = g_logits[b * RULES + lane] + gumbel[b * RULES + lane];
    int bi = lane;
    #pragma unroll
    for (int off = 16; off; off >>= 1) {
        float ov = __shfl_xor_sync(0xffffffffu, bv, off);
        int   oi = __shfl_xor_sync(0xffffffffu, bi, off);
        if (ov > bv || (ov == bv && oi < bi)) { bv = ov; bi = oi; }
    }
    int rbest = bi;

    float4 hv = *reinterpret_cast<const float4*>(
        g_hnext + ((size_t)b * RULES + rbest) * KDIM + lane * 4);
    *reinterpret_cast<float4*>(out_h + (size_t)b * KDIM + lane * 4) = hv;
    if (out_attn && lane < RULES)
        out_attn[b * RULES + lane] = (lane == rbest) ? 1.0f : 0.0f;
}

// ---------------------------------------------------------------------------
extern "C" void kernel_launch(void* const* d_in, const int* in_sizes, int n_in,
                              void* d_out, int out_size) {
    const float* X      = (const float*)d_in[0];
    const float* H      = (const float*)d_in[1];
    const float* Wih    = (const float*)d_in[2];
    const float* Whh    = (const float*)d_in[3];
    const float* bih    = (const float*)d_in[4];
    const float* bhh    = (const float*)d_in[5];
    const float* wread  = (const float*)d_in[6];
    const float* wwrite = (const float*)d_in[7];
    const float* gum    = (const float*)d_in[8];
    float* out = (float*)d_out;

    cudaFuncSetAttribute(kGRU, cudaFuncAttributeMaxDynamicSharedMemorySize, SMEM_TOTAL);

    kPre<<<NA / 256 + 1, 256>>>(X, H, Wih, Whh, wread, wwrite);
    kQ<<<BTOT / 16, 256>>>(H);

    dim3 grid(BTOT / TM, RULES);
    kGRU<<<grid, 512, SMEM_TOTAL>>>(H, bih, bhh);

    const int HO = BTOT * KDIM;
    float* attn = (out_size >= HO + BTOT * RULES) ? out + HO : nullptr;
    kSelect<<<BTOT / 8, 256>>>(gum, out, attn);
}